// round 13
// baseline (speedup 1.0000x reference)
#include <cuda_runtime.h>
#include <math.h>

typedef unsigned long long u64;

// Round 13: two-kernel split.
// K1: xi = conv1x1(x) (256ch GEMM) -> g_xi[256][262144] (fp32, planar).
// K2: fused dwconvs + gelu-gating + grouped proj, staging xc tiles from g_xi
//     (pn channels recomputed on the fly).

__device__ float g_xi[256 * 262144];   // 268 MB scratch

__device__ __forceinline__ u64 pk2(float lo, float hi) {
    u64 r; asm("mov.b64 %0,{%1,%2};" : "=l"(r) : "f"(lo), "f"(hi)); return r;
}
__device__ __forceinline__ void upk2(u64 v, float& lo, float& hi) {
    asm("mov.b64 {%0,%1},%2;" : "=f"(lo), "=f"(hi) : "l"(v));
}
__device__ __forceinline__ void fma2(u64& d, u64 a, u64 b) {
    asm("fma.rn.f32x2 %0,%1,%2,%0;" : "+l"(d) : "l"(a), "l"(b));
}

__device__ __forceinline__ float gelu_exact(float v) {
    return 0.5f * v * (1.0f + erff(v * 0.70710678118654752f));
}

// ============================ Kernel 1: GEMM ============================
// Block: 64 och x 256 px. Thread (ty=och-oct, tx=px-oct): 8 och x 8 px.
// Pack och-pairs in f32x2 (weights load directly as u64 pairs from [k][och]).
#define K1_XS 0          // [64 k][256 px] = 16384
#define K1_WT 16384      // [64 k][64 och] = 4096
#define K1_TOTAL 20480   // 81920 bytes -> 2 blocks/SM

__global__ void __launch_bounds__(256, 2)
conv1x1_kernel(const float* __restrict__ x,
               const float* __restrict__ w_in,
               const float* __restrict__ b_in)
{
    extern __shared__ float sm[];
    const int tid = threadIdx.x;
    const int pb = blockIdx.x;           // 1024 px-blocks (256 px each)
    const int ob = blockIdx.y;           // 4 och-blocks (64 och each)
    const int base = pb * 256;           // global pixel base
    const int b    = base >> 16;
    const int off  = base & 65535;

    // stage X tile [k][px]
    {
        const float* xb = x + (size_t)b * 64 * 65536 + off;
        for (int v = tid; v < 16384; v += 256) {
            int k = v >> 8, px = v & 255;
            sm[K1_XS + v] = xb[(size_t)k * 65536 + px];
        }
    }
    // stage W tile transposed [k][och]
    for (int v = tid; v < 4096; v += 256) {
        int k = v >> 6, oc = v & 63;
        sm[K1_WT + k * 64 + oc] = w_in[(ob * 64 + oc) * 64 + k];
    }
    __syncthreads();

    const int ty = tid >> 5;             // och-oct 0..7
    const int tx = tid & 31;             // px-oct 0..31
    const int ochBase = ob * 64 + ty * 8;

    u64 acc[4][8];
#pragma unroll
    for (int op = 0; op < 4; ++op) {
        u64 bp = *(const u64*)(b_in + ochBase + 2 * op);
#pragma unroll
        for (int px = 0; px < 8; ++px) acc[op][px] = bp;
    }

    const float* XS = sm + K1_XS + tx * 8;
    const float* WT = sm + K1_WT + ty * 8;
#pragma unroll 2
    for (int k = 0; k < 64; ++k) {
        float4 p03 = *(const float4*)(XS + k * 256);
        float4 p47 = *(const float4*)(XS + k * 256 + 4);
        ulonglong2 w01 = *(const ulonglong2*)(WT + k * 64);
        ulonglong2 w23 = *(const ulonglong2*)(WT + k * 64 + 4);
        u64 pp[8];
        pp[0] = pk2(p03.x, p03.x); pp[1] = pk2(p03.y, p03.y);
        pp[2] = pk2(p03.z, p03.z); pp[3] = pk2(p03.w, p03.w);
        pp[4] = pk2(p47.x, p47.x); pp[5] = pk2(p47.y, p47.y);
        pp[6] = pk2(p47.z, p47.z); pp[7] = pk2(p47.w, p47.w);
#pragma unroll
        for (int px = 0; px < 8; ++px) {
            fma2(acc[0][px], w01.x, pp[px]);
            fma2(acc[1][px], w01.y, pp[px]);
            fma2(acc[2][px], w23.x, pp[px]);
            fma2(acc[3][px], w23.y, pp[px]);
        }
    }

    // epilogue: 8 och rows x 8 px each
    const size_t pixBase = (size_t)base + tx * 8;
#pragma unroll
    for (int op = 0; op < 4; ++op) {
        float lo[8], hi[8];
#pragma unroll
        for (int px = 0; px < 8; ++px) upk2(acc[op][px], lo[px], hi[px]);
        float* r0 = g_xi + (size_t)(ochBase + 2 * op) * 262144 + pixBase;
        float* r1 = r0 + 262144;
        *(float4*)(r0)     = make_float4(lo[0], lo[1], lo[2], lo[3]);
        *(float4*)(r0 + 4) = make_float4(lo[4], lo[5], lo[6], lo[7]);
        *(float4*)(r1)     = make_float4(hi[0], hi[1], hi[2], hi[3]);
        *(float4*)(r1 + 4) = make_float4(hi[4], hi[5], hi[6], hi[7]);
    }
}

// ============================ Kernel 2: fused rest ============================
#define HALO   240     // 20 x 12
#define K2_XC     0        // 24*240 = 5760
#define K2_SPN    5760     // 2*240 = 480
#define K2_D3A    6240     // 1440
#define K2_D1     7680     // 1024
#define K2_GDW1   8704     // 8*28 = 224
#define K2_GDW3A  8928     // 224
#define K2_GDW3B  9152     // 96
#define K2_GWOUT  9248     // 256
#define K2_BDW1   9504     // 128
#define K2_BDW3A  9632     // 128
#define K2_BDW3B  9760     // 128
#define K2_BOUT   9888     // 64
#define K2_WPN    9952     // 256
#define K2_BPN    10208    // 128
#define K2_TOTAL  10336    // 41344 bytes -> 2 blocks/SM (reg-limited)

__global__ void __launch_bounds__(256, 2)
ffn_rest_kernel(const float* __restrict__ pneff,
                const float* __restrict__ w_pn,  const float* __restrict__ b_pn,
                const float* __restrict__ w_dw1, const float* __restrict__ b_dw1,
                const float* __restrict__ w_dw3a,const float* __restrict__ b_dw3a,
                const float* __restrict__ w_dw3b,const float* __restrict__ b_dw3b,
                const float* __restrict__ w_out, const float* __restrict__ b_out,
                float* __restrict__ out)
{
    extern __shared__ float sm[];
    const int tid = threadIdx.x;
    const int bx0 = blockIdx.x * 16;
    const int by0 = blockIdx.y * 8;
    const int b   = blockIdx.z;

    if (tid < 128) {
        sm[K2_BDW1 + tid]  = b_dw1[tid];
        sm[K2_BDW3A + tid] = b_dw3a[tid];
        sm[K2_BDW3B + tid] = b_dw3b[tid];
        sm[K2_BPN + tid]   = b_pn[tid];
    }
    if (tid < 64) sm[K2_BOUT + tid] = b_out[tid];
    sm[K2_WPN + tid] = w_pn[tid];

    // pn tile (2 ch, 240 halo px)
    {
        const float* pnb = pneff + (size_t)b * 2 * 65536;
        for (int v = tid; v < 2 * HALO; v += 256) {
            int c = v / HALO, p = v - c * HALO;
            int ry = p / 20, rx = p - ry * 20;
            int gy = by0 + ry - 2, gx = bx0 + rx - 2;
            float vv = 0.0f;
            if ((unsigned)gy < 256u && (unsigned)gx < 256u)
                vv = pnb[(size_t)c * 65536 + gy * 256 + gx];
            sm[K2_SPN + c * HALO + p] = vv;
        }
    }
    __syncthreads();

    const int tA   = tid & 127;
    const int gh   = tid >> 7;
    const int tyl  = tA >> 4;
    const int tx   = tA & 15;
    const int warp = tid >> 5;
    const int lane = tid & 31;

    u64 acc[16];
#pragma unroll
    for (int i = 0; i < 16; ++i) acc[i] = 0ULL;

    for (int g = 0; g < 16; ++g) {
        // ---- stage per-group weights + xc tile ----
        {
            for (int v = tid; v < 216; v += 256) {
                int cc = v / 27, t = v - cc * 27;
                int ch = 4 * g + (cc >> 1) + (cc & 1) * 64;
                sm[K2_GDW1 + cc * 28 + t]  = w_dw1[ch * 27 + t];
                sm[K2_GDW3A + cc * 28 + t] = w_dw3a[ch * 27 + t];
            }
            if (tid < 72) {
                int cc = tid / 9, t = tid - cc * 9;
                int ch = 4 * g + (cc >> 1) + (cc & 1) * 64;
                sm[K2_GDW3B + cc * 12 + t] = w_dw3b[ch * 9 + t];
            }
            {
                int cpl = tid >> 6, o = tid & 63;
                sm[K2_GWOUT + tid] = w_out[o * 64 + 4 * g + cpl];
            }
            // xc tile: 24 slots x 240 px
            for (int v = tid; v < 5760; v += 256) {
                int slot = v / 240, p = v - slot * 240;
                int ry = p / 20, rx = p - ry * 20;
                int gy = by0 + ry - 2, gx = bx0 + rx - 2;
                float val = 0.0f;
                if ((unsigned)gy < 256u && (unsigned)gx < 256u) {
                    int c = (slot < 12) ? (12 * g + slot) : (180 + 12 * g + slot);
                    if (c < 128) {
                        float pn0 = sm[K2_SPN + p];
                        float pn1 = sm[K2_SPN + HALO + p];
                        val = fmaf(sm[K2_WPN + 2 * c], pn0,
                              fmaf(sm[K2_WPN + 2 * c + 1], pn1, sm[K2_BPN + c]));
                    } else {
                        int j = c - 128;
                        val = g_xi[(size_t)j * 262144 + (size_t)b * 65536
                                   + gy * 256 + gx];
                    }
                }
                sm[K2_XC + slot * 240 + p] = val;
            }
        }
        __syncthreads();   // weights + XC ready

        // ---- B1: warp = (cpl, chain), sliding window, raw d1 -> D1 ----
        {
            const int cpl = warp >> 1, ch = warp & 1;
            const int cc = cpl * 2 + ch;
            float wr[28];
#pragma unroll
            for (int i = 0; i < 7; ++i) {
                float4 w4 = ((const float4*)(sm + K2_GDW1 + cc * 28))[i];
                wr[4 * i] = w4.x; wr[4 * i + 1] = w4.y;
                wr[4 * i + 2] = w4.z; wr[4 * i + 3] = w4.w;
            }
            const float bias = sm[K2_BDW1 + 4 * g + cpl + ch * 64];
            const float* xb = sm + K2_XC + (ch * 12 + 3 * cpl) * 240;
            float* dst = sm + K2_D1 + cc * 128;
            const bool ld = (lane < 18);
            float a0v[3], a1v[3], a2v[3], b0v[3], b1v[3], b2v[3], c0v[3], c1v[3], c2v[3];
#pragma unroll
            for (int j = 0; j < 3; ++j) {
                float v = ld ? xb[j * 240 + 20 + lane + 1] : 0.f;
                a0v[j] = v;
                a1v[j] = __shfl_down_sync(0xffffffffu, v, 1);
                a2v[j] = __shfl_down_sync(0xffffffffu, v, 2);
                float w = ld ? xb[j * 240 + 40 + lane + 1] : 0.f;
                b0v[j] = w;
                b1v[j] = __shfl_down_sync(0xffffffffu, w, 1);
                b2v[j] = __shfl_down_sync(0xffffffffu, w, 2);
            }
#pragma unroll
            for (int r = 0; r < 8; ++r) {
#pragma unroll
                for (int j = 0; j < 3; ++j) {
                    float v = ld ? xb[j * 240 + (r + 3) * 20 + lane + 1] : 0.f;
                    c0v[j] = v;
                    c1v[j] = __shfl_down_sync(0xffffffffu, v, 1);
                    c2v[j] = __shfl_down_sync(0xffffffffu, v, 2);
                }
                float d = bias;
#pragma unroll
                for (int j = 0; j < 3; ++j) {
                    d = fmaf(wr[j * 9 + 0], a0v[j], d);
                    d = fmaf(wr[j * 9 + 1], a1v[j], d);
                    d = fmaf(wr[j * 9 + 2], a2v[j], d);
                    d = fmaf(wr[j * 9 + 3], b0v[j], d);
                    d = fmaf(wr[j * 9 + 4], b1v[j], d);
                    d = fmaf(wr[j * 9 + 5], b2v[j], d);
                    d = fmaf(wr[j * 9 + 6], c0v[j], d);
                    d = fmaf(wr[j * 9 + 7], c1v[j], d);
                    d = fmaf(wr[j * 9 + 8], c2v[j], d);
                }
                if (lane < 16) dst[r * 16 + lane] = d;
#pragma unroll
                for (int j = 0; j < 3; ++j) {
                    a0v[j] = b0v[j]; a1v[j] = b1v[j]; a2v[j] = b2v[j];
                    b0v[j] = c0v[j]; b1v[j] = c1v[j]; b2v[j] = c2v[j];
                }
            }
        }

        // ---- B2: warp = (cpl, h), sliding window -> D3A ----
        {
            const int cpl = warp >> 1, h = warp & 1;
            const int cc = cpl * 2 + h;
            const int cp = 4 * g + cpl;
            float wr[28];
#pragma unroll
            for (int i = 0; i < 7; ++i) {
                float4 w4 = ((const float4*)(sm + K2_GDW3A + cc * 28))[i];
                wr[4 * i] = w4.x; wr[4 * i + 1] = w4.y;
                wr[4 * i + 2] = w4.z; wr[4 * i + 3] = w4.w;
            }
            const float bias = sm[K2_BDW3A + cp + h * 64];
            const float* xb = sm + K2_XC + (h * 12 + 3 * cpl) * 240;
            float* dst = sm + K2_D3A + cpl * 360 + h * 180;
            const bool ld  = (lane < 20);
            const bool stv = (lane < 18);
            const int gxc  = bx0 + lane - 1;
            const bool colOK = stv && ((unsigned)gxc < 256u);

            float v0[3], v1[3], v2[3], p0v[3], p1v[3], p2v[3], r0[3], r1[3], r2[3];
#pragma unroll
            for (int j = 0; j < 3; ++j) {
                float a = ld ? xb[j * 240 + lane] : 0.0f;
                v0[j] = a;
                p0v[j] = __shfl_down_sync(0xffffffffu, a, 1);
                r0[j] = __shfl_down_sync(0xffffffffu, a, 2);
                float bva = ld ? xb[j * 240 + 20 + lane] : 0.0f;
                v1[j] = bva;
                p1v[j] = __shfl_down_sync(0xffffffffu, bva, 1);
                r1[j] = __shfl_down_sync(0xffffffffu, bva, 2);
            }
#pragma unroll
            for (int qy = 0; qy < 10; ++qy) {
#pragma unroll
                for (int j = 0; j < 3; ++j) {
                    float c = ld ? xb[j * 240 + (qy + 2) * 20 + lane] : 0.0f;
                    v2[j] = c;
                    p2v[j] = __shfl_down_sync(0xffffffffu, c, 1);
                    r2[j] = __shfl_down_sync(0xffffffffu, c, 2);
                }
                float d = bias;
#pragma unroll
                for (int j = 0; j < 3; ++j) {
                    d = fmaf(wr[j * 9 + 0], v0[j], d);
                    d = fmaf(wr[j * 9 + 1], p0v[j], d);
                    d = fmaf(wr[j * 9 + 2], r0[j], d);
                    d = fmaf(wr[j * 9 + 3], v1[j], d);
                    d = fmaf(wr[j * 9 + 4], p1v[j], d);
                    d = fmaf(wr[j * 9 + 5], r1[j], d);
                    d = fmaf(wr[j * 9 + 6], v2[j], d);
                    d = fmaf(wr[j * 9 + 7], p2v[j], d);
                    d = fmaf(wr[j * 9 + 8], r2[j], d);
                }
                if (stv) {
                    int gy = by0 + qy - 1;
                    bool ok = colOK && ((unsigned)gy < 256u);
                    dst[qy * 18 + lane] = ok ? d : 0.0f;
                }
#pragma unroll
                for (int j = 0; j < 3; ++j) {
                    v0[j] = v1[j]; p0v[j] = p1v[j]; r0[j] = r1[j];
                    v1[j] = v2[j]; p1v[j] = p2v[j]; r1[j] = r2[j];
                }
            }
        }
        __syncthreads();   // D1 + D3A ready

        if (gh == 0) {
            // ---- gating + packed proj (o 0..31) ----
#pragma unroll
            for (int cpl = 0; cpl < 4; ++cpl) {
                float d1a = sm[K2_D1 + (cpl * 2 + 0) * 128 + tA];
                float d1b = sm[K2_D1 + (cpl * 2 + 1) * 128 + tA];
                float g1 = gelu_exact(d1a) * d1b;
                u64 g1p = pk2(g1, g1);
                const ulonglong2* wo = (const ulonglong2*)(sm + K2_GWOUT + cpl * 64);
#pragma unroll
                for (int mm = 0; mm < 8; ++mm) {
                    ulonglong2 w2 = wo[mm];
                    fma2(acc[2 * mm], w2.x, g1p);
                    fma2(acc[2 * mm + 1], w2.y, g1p);
                }
            }
        } else {
            // ---- B3 + packed proj (o 32..63) ----
#pragma unroll
            for (int cpl = 0; cpl < 4; ++cpl) {
                const int cp = 4 * g + cpl;
                float wA[12], wB[12];
#pragma unroll
                for (int i = 0; i < 3; ++i) {
                    float4 w4 = ((const float4*)(sm + K2_GDW3B + (cpl * 2) * 12))[i];
                    wA[4 * i] = w4.x; wA[4 * i + 1] = w4.y;
                    wA[4 * i + 2] = w4.z; wA[4 * i + 3] = w4.w;
                    float4 v4 = ((const float4*)(sm + K2_GDW3B + (cpl * 2 + 1) * 12))[i];
                    wB[4 * i] = v4.x; wB[4 * i + 1] = v4.y;
                    wB[4 * i + 2] = v4.z; wB[4 * i + 3] = v4.w;
                }
                float dA = sm[K2_BDW3B + cp];
                float dB = sm[K2_BDW3B + cp + 64];
                const float* dz = sm + K2_D3A + cpl * 360;
#pragma unroll
                for (int ky = 0; ky < 3; ++ky)
#pragma unroll
                    for (int kx = 0; kx < 3; ++kx) {
                        int qi = (tyl + ky) * 18 + (tx + kx);
                        int t = ky * 3 + kx;
                        dA = fmaf(wA[t], dz[qi], dA);
                        dB = fmaf(wB[t], dz[180 + qi], dB);
                    }
                float g2 = gelu_exact(dA) * dB;
                u64 g2p = pk2(g2, g2);
                const ulonglong2* wo = (const ulonglong2*)(sm + K2_GWOUT + cpl * 64 + 32);
#pragma unroll
                for (int mm = 0; mm < 8; ++mm) {
                    ulonglong2 w2 = wo[mm];
                    fma2(acc[2 * mm], w2.x, g2p);
                    fma2(acc[2 * mm + 1], w2.y, g2p);
                }
            }
        }
        __syncthreads();   // protect weights/XC/D1/D3A before next staging
    }

    float* ob = out + (size_t)b * 64 * 65536 + (size_t)(by0 + tyl) * 256 + (bx0 + tx);
    const int o0 = gh * 32;
#pragma unroll
    for (int mm = 0; mm < 16; ++mm) {
        float lo, hi;
        upk2(acc[mm], lo, hi);
        ob[(size_t)(o0 + 2 * mm) * 65536]     = lo + sm[K2_BOUT + o0 + 2 * mm];
        ob[(size_t)(o0 + 2 * mm + 1) * 65536] = hi + sm[K2_BOUT + o0 + 2 * mm + 1];
    }
}

extern "C" void kernel_launch(void* const* d_in, const int* in_sizes, int n_in,
                              void* d_out, int out_size)
{
    (void)in_sizes; (void)n_in; (void)out_size;
    const float* x      = (const float*)d_in[0];
    const float* pneff  = (const float*)d_in[1];
    const float* w_in   = (const float*)d_in[2];
    const float* b_in   = (const float*)d_in[3];
    const float* w_pn   = (const float*)d_in[4];
    const float* b_pn   = (const float*)d_in[5];
    const float* w_dw1  = (const float*)d_in[6];
    const float* b_dw1  = (const float*)d_in[7];
    const float* w_dw3a = (const float*)d_in[8];
    const float* b_dw3a = (const float*)d_in[9];
    const float* w_dw3b = (const float*)d_in[10];
    const float* b_dw3b = (const float*)d_in[11];
    const float* w_out  = (const float*)d_in[12];
    const float* b_out  = (const float*)d_in[13];
    float* out = (float*)d_out;

    cudaFuncSetAttribute(conv1x1_kernel,
                         cudaFuncAttributeMaxDynamicSharedMemorySize,
                         K1_TOTAL * (int)sizeof(float));
    cudaFuncSetAttribute(ffn_rest_kernel,
                         cudaFuncAttributeMaxDynamicSharedMemorySize,
                         K2_TOTAL * (int)sizeof(float));

    dim3 g1(1024, 4);
    conv1x1_kernel<<<g1, 256, K1_TOTAL * sizeof(float)>>>(x, w_in, b_in);

    dim3 g2(16, 32, 4);
    ffn_rest_kernel<<<g2, 256, K2_TOTAL * sizeof(float)>>>(
        pneff, w_pn, b_pn, w_dw1, b_dw1,
        w_dw3a, b_dw3a, w_dw3b, b_dw3b, w_out, b_out, out);
}

// round 14
// speedup vs baseline: 1.5562x; 1.5562x over previous
#include <cuda_runtime.h>
#include <math.h>

typedef unsigned long long u64;

// Round 14: R12 base, with B1 merged into B2's sliding-window pass
// (one XC window load feeds both dw1 and dw3a convolutions).

#define HALO   240     // 20 x 12
#define SM_SX     0        // 64*240 = 15360
#define SM_SPN    15360    // 480
#define SM_XC     15840    // 5760
#define SM_D3A    21600    // 1440
#define SM_D1     23040    // 1024
#define SM_WT     24064    // 1536
#define SM_GDW1   25600    // 8*28 = 224
#define SM_GDW3A  25824    // 224
#define SM_GDW3B  26048    // 96
#define SM_GWOUT  26144    // 256
#define SM_BDW1   26400    // 128
#define SM_BDW3A  26528    // 128
#define SM_BDW3B  26656    // 128
#define SM_BOUT   26784    // 64
#define SM_WPN    26848    // 256
#define SM_BPN    27104    // 128
#define SM_BIN    27232    // 256
#define SM_TOTAL  27488    // 109952 bytes -> 2 blocks/SM

__device__ __forceinline__ u64 pk2(float lo, float hi) {
    u64 r; asm("mov.b64 %0,{%1,%2};" : "=l"(r) : "f"(lo), "f"(hi)); return r;
}
__device__ __forceinline__ void upk2(u64 v, float& lo, float& hi) {
    asm("mov.b64 {%0,%1},%2;" : "=f"(lo), "=f"(hi) : "l"(v));
}
__device__ __forceinline__ void fma2(u64& d, u64 a, u64 b) {
    asm("fma.rn.f32x2 %0,%1,%2,%0;" : "+l"(d) : "l"(a), "l"(b));
}
__device__ __forceinline__ u64 lds64(const float* p) { return *(const u64*)p; }

__device__ __forceinline__ float gelu_exact(float v) {
    return 0.5f * v * (1.0f + erff(v * 0.70710678118654752f));
}

// Phase A, B-half (12 xi channels, 6 pairs) for adjacent pixels p0, p0+1.
__device__ __forceinline__ void phaseA_B(float* sm, int g, int p0,
                                         float m0, float m1)
{
    u64 a0[6], a1[6];
#pragma unroll
    for (int j = 0; j < 6; ++j) {
        u64 bp = lds64(sm + SM_BIN + 64 + 12 * g + 2 * j);
        a0[j] = bp; a1[j] = bp;
    }
#pragma unroll 4
    for (int k = 0; k < 64; ++k) {
        float2 s = *(const float2*)(sm + SM_SX + k * 240 + p0);
        u64 s0 = pk2(s.x, s.x);
        u64 s1 = pk2(s.y, s.y);
        const float* wt = sm + SM_WT + k * 24;
        ulonglong2 w01 = *(const ulonglong2*)(wt);
        ulonglong2 w23 = *(const ulonglong2*)(wt + 4);
        ulonglong2 w45 = *(const ulonglong2*)(wt + 8);
        fma2(a0[0], w01.x, s0); fma2(a1[0], w01.x, s1);
        fma2(a0[1], w01.y, s0); fma2(a1[1], w01.y, s1);
        fma2(a0[2], w23.x, s0); fma2(a1[2], w23.x, s1);
        fma2(a0[3], w23.y, s0); fma2(a1[3], w23.y, s1);
        fma2(a0[4], w45.x, s0); fma2(a1[4], w45.x, s1);
        fma2(a0[5], w45.y, s0); fma2(a1[5], w45.y, s1);
    }
#pragma unroll
    for (int j = 0; j < 6; ++j) {
        float lo0, hi0, lo1, hi1;
        upk2(a0[j], lo0, hi0);
        upk2(a1[j], lo1, hi1);
        float* c0 = sm + SM_XC + (12 + 2 * j) * 240 + p0;
        float* c1 = sm + SM_XC + (13 + 2 * j) * 240 + p0;
        c0[0] = lo0 * m0; c0[1] = lo1 * m1;
        c1[0] = hi0 * m0; c1[1] = hi1 * m1;
    }
}

// Phase A, A-half. NP = xi channel pairs {0, 2, 6}.
template<int NP>
__device__ __forceinline__ void phaseA_A(float* sm, int g, int p0,
                                         float m0, float m1,
                                         float pn00, float pn01,
                                         float pn10, float pn11)
{
    float xv0[12], xv1[12];
    if (NP > 0) {
        u64 a0[NP > 0 ? NP : 1], a1[NP > 0 ? NP : 1];
        const int base = (NP == 2) ? 0 : (12 * g - 128);
#pragma unroll
        for (int j = 0; j < NP; ++j) {
            u64 bp = lds64(sm + SM_BIN + base + 2 * j);
            a0[j] = bp; a1[j] = bp;
        }
#pragma unroll 4
        for (int k = 0; k < 64; ++k) {
            float2 s = *(const float2*)(sm + SM_SX + k * 240 + p0);
            u64 s0 = pk2(s.x, s.x);
            u64 s1 = pk2(s.y, s.y);
            const float* wt = sm + SM_WT + k * 24 + 12;
            if (NP == 2) {
                ulonglong2 w = *(const ulonglong2*)(wt);
                fma2(a0[0], w.x, s0); fma2(a1[0], w.x, s1);
                fma2(a0[1], w.y, s0); fma2(a1[1], w.y, s1);
            } else {
                ulonglong2 w01 = *(const ulonglong2*)(wt);
                ulonglong2 w23 = *(const ulonglong2*)(wt + 4);
                ulonglong2 w45 = *(const ulonglong2*)(wt + 8);
                fma2(a0[0], w01.x, s0); fma2(a1[0], w01.x, s1);
                fma2(a0[1], w01.y, s0); fma2(a1[1], w01.y, s1);
                fma2(a0[2], w23.x, s0); fma2(a1[2], w23.x, s1);
                fma2(a0[3], w23.y, s0); fma2(a1[3], w23.y, s1);
                fma2(a0[4], w45.x, s0); fma2(a1[4], w45.x, s1);
                fma2(a0[5], w45.y, s0); fma2(a1[5], w45.y, s1);
            }
        }
        const int s0i = (NP == 2) ? 8 : 0;
#pragma unroll
        for (int j = 0; j < NP; ++j) {
            upk2(a0[j], xv0[s0i + 2 * j], xv0[s0i + 2 * j + 1]);
            upk2(a1[j], xv1[s0i + 2 * j], xv1[s0i + 2 * j + 1]);
        }
    }
#pragma unroll
    for (int s = 0; s < 12; ++s) {
        const bool isPN = (NP == 0) || (NP == 2 && s < 8);
        if (isPN) {
            int c = 12 * g + s;
            float w0 = sm[SM_WPN + 2 * c], w1 = sm[SM_WPN + 2 * c + 1];
            float bb = sm[SM_BPN + c];
            xv0[s] = fmaf(w0, pn00, fmaf(w1, pn10, bb));
            xv1[s] = fmaf(w0, pn01, fmaf(w1, pn11, bb));
        }
        float* cp = sm + SM_XC + s * 240 + p0;
        cp[0] = xv0[s] * m0;
        cp[1] = xv1[s] * m1;
    }
}

__global__ void __launch_bounds__(256, 2)
ffn_fused_kernel(const float* __restrict__ x,
                 const float* __restrict__ pneff,
                 const float* __restrict__ w_in,  const float* __restrict__ b_in,
                 const float* __restrict__ w_pn,  const float* __restrict__ b_pn,
                 const float* __restrict__ w_dw1, const float* __restrict__ b_dw1,
                 const float* __restrict__ w_dw3a,const float* __restrict__ b_dw3a,
                 const float* __restrict__ w_dw3b,const float* __restrict__ b_dw3b,
                 const float* __restrict__ w_out, const float* __restrict__ b_out,
                 float* __restrict__ out)
{
    extern __shared__ float sm[];
    const int tid = threadIdx.x;
    const int bx0 = blockIdx.x * 16;
    const int by0 = blockIdx.y * 8;
    const int b   = blockIdx.z;

    if (tid < 128) {
        sm[SM_BDW1 + tid]  = b_dw1[tid];
        sm[SM_BDW3A + tid] = b_dw3a[tid];
        sm[SM_BDW3B + tid] = b_dw3b[tid];
        sm[SM_BPN + tid]   = b_pn[tid];
    }
    if (tid < 64) sm[SM_BOUT + tid] = b_out[tid];
    sm[SM_WPN + tid] = w_pn[tid];
    sm[SM_BIN + tid] = b_in[tid];

    {
        const float* xb = x + (size_t)b * 64 * 65536;
        for (int v = tid; v < 64 * HALO; v += 256) {
            int c = v / HALO, p = v - c * HALO;
            int ry = p / 20, rx = p - ry * 20;
            int gy = by0 + ry - 2, gx = bx0 + rx - 2;
            float vv = 0.0f;
            if ((unsigned)gy < 256u && (unsigned)gx < 256u)
                vv = xb[(size_t)c * 65536 + gy * 256 + gx];
            sm[SM_SX + c * HALO + p] = vv;
        }
        const float* pnb = pneff + (size_t)b * 2 * 65536;
        for (int v = tid; v < 2 * HALO; v += 256) {
            int c = v / HALO, p = v - c * HALO;
            int ry = p / 20, rx = p - ry * 20;
            int gy = by0 + ry - 2, gx = bx0 + rx - 2;
            float vv = 0.0f;
            if ((unsigned)gy < 256u && (unsigned)gx < 256u)
                vv = pnb[(size_t)c * 65536 + gy * 256 + gx];
            sm[SM_SPN + c * HALO + p] = vv;
        }
    }
    __syncthreads();

    const int tA  = tid & 127;
    const int gh  = tid >> 7;
    const bool doA = (tA < 120);
    const int p0  = doA ? (2 * tA) : 0;
    float m0, m1;
    {
        int ry = p0 / 20, rx = p0 - ry * 20;
        m0 = ((unsigned)(by0 + ry - 2) < 256u && (unsigned)(bx0 + rx - 2) < 256u) ? 1.f : 0.f;
        int p1 = p0 + 1;
        int ry1 = p1 / 20, rx1 = p1 - ry1 * 20;
        m1 = ((unsigned)(by0 + ry1 - 2) < 256u && (unsigned)(bx0 + rx1 - 2) < 256u) ? 1.f : 0.f;
    }
    const float pn00 = sm[SM_SPN + p0],        pn01 = sm[SM_SPN + p0 + 1];
    const float pn10 = sm[SM_SPN + HALO + p0], pn11 = sm[SM_SPN + HALO + p0 + 1];

    const int tyl  = tA >> 4;
    const int tx   = tA & 15;
    const int warp = tid >> 5;
    const int lane = tid & 31;

    u64 acc[16];
#pragma unroll
    for (int i = 0; i < 16; ++i) acc[i] = 0ULL;

    for (int g = 0; g < 16; ++g) {
        // ---- stage per-group weights ----
        {
            const int nw = (g < 10) ? 768 : (g == 10 ? 1024 : 1536);
            const int ncol = nw / 64;
            for (int v = tid; v < nw; v += 256) {
                int k = v / ncol, j = v - k * ncol;
                int xi = (j < 12) ? (64 + 12 * g + j)
                                  : ((g == 10) ? (j - 12) : (12 * g - 128 + j - 12));
                sm[SM_WT + k * 24 + j] = w_in[xi * 64 + k];
            }
            for (int v = tid; v < 216; v += 256) {
                int cc = v / 27, t = v - cc * 27;
                int ch = 4 * g + (cc >> 1) + (cc & 1) * 64;
                sm[SM_GDW1 + cc * 28 + t]  = w_dw1[ch * 27 + t];
                sm[SM_GDW3A + cc * 28 + t] = w_dw3a[ch * 27 + t];
            }
            if (tid < 72) {
                int cc = tid / 9, t = tid - cc * 9;
                int ch = 4 * g + (cc >> 1) + (cc & 1) * 64;
                sm[SM_GDW3B + cc * 12 + t] = w_dw3b[ch * 9 + t];
            }
            {
                int cpl = tid >> 6, o = tid & 63;
                sm[SM_GWOUT + tid] = w_out[o * 64 + 4 * g + cpl];
            }
        }
        __syncthreads();   // weights ready

        // ---- Phase A (channel-split, packed pairs) ----
        if (gh == 0) {
            if (doA) phaseA_B(sm, g, p0, m0, m1);
        } else if (doA) {
            if (g < 10)       phaseA_A<0>(sm, g, p0, m0, m1, pn00, pn01, pn10, pn11);
            else if (g == 10) phaseA_A<2>(sm, g, p0, m0, m1, pn00, pn01, pn10, pn11);
            else              phaseA_A<6>(sm, g, p0, m0, m1, pn00, pn01, pn10, pn11);
        }
        __syncthreads();   // XC ready

        // ---- Merged B1+B2: warp = (cpl, h); one window feeds both convs ----
        {
            const int cpl = warp >> 1, h = warp & 1;
            const int cc = cpl * 2 + h;
            const int cp = 4 * g + cpl;
            float w3[28], w1[28];
#pragma unroll
            for (int i = 0; i < 7; ++i) {
                float4 a4 = ((const float4*)(sm + SM_GDW3A + cc * 28))[i];
                w3[4 * i] = a4.x; w3[4 * i + 1] = a4.y;
                w3[4 * i + 2] = a4.z; w3[4 * i + 3] = a4.w;
                float4 b4 = ((const float4*)(sm + SM_GDW1 + cc * 28))[i];
                w1[4 * i] = b4.x; w1[4 * i + 1] = b4.y;
                w1[4 * i + 2] = b4.z; w1[4 * i + 3] = b4.w;
            }
            const float bias3 = sm[SM_BDW3A + cp + h * 64];
            const float bias1 = sm[SM_BDW1 + cp + h * 64];
            const float* xb = sm + SM_XC + (h * 12 + 3 * cpl) * 240;
            float* dst3 = sm + SM_D3A + cpl * 360 + h * 180;
            float* dst1 = sm + SM_D1 + cc * 128;
            const bool ld  = (lane < 20);
            const bool stv = (lane < 18);
            const bool st1 = (lane >= 1 && lane <= 16);
            const int gxc  = bx0 + lane - 1;
            const bool colOK = stv && ((unsigned)gxc < 256u);

            float v0[3], v1[3], v2[3], q0v[3], q1v[3], q2v[3], r0[3], r1[3], r2[3];
#pragma unroll
            for (int j = 0; j < 3; ++j) {
                float a = ld ? xb[j * 240 + lane] : 0.0f;
                v0[j] = a;
                q0v[j] = __shfl_down_sync(0xffffffffu, a, 1);
                r0[j] = __shfl_down_sync(0xffffffffu, a, 2);
                float bva = ld ? xb[j * 240 + 20 + lane] : 0.0f;
                v1[j] = bva;
                q1v[j] = __shfl_down_sync(0xffffffffu, bva, 1);
                r1[j] = __shfl_down_sync(0xffffffffu, bva, 2);
            }
#pragma unroll
            for (int qy = 0; qy < 10; ++qy) {
#pragma unroll
                for (int j = 0; j < 3; ++j) {
                    float c = ld ? xb[j * 240 + (qy + 2) * 20 + lane] : 0.0f;
                    v2[j] = c;
                    q2v[j] = __shfl_down_sync(0xffffffffu, c, 1);
                    r2[j] = __shfl_down_sync(0xffffffffu, c, 2);
                }
                float d3 = bias3;
#pragma unroll
                for (int j = 0; j < 3; ++j) {
                    d3 = fmaf(w3[j * 9 + 0], v0[j], d3);
                    d3 = fmaf(w3[j * 9 + 1], q0v[j], d3);
                    d3 = fmaf(w3[j * 9 + 2], r0[j], d3);
                    d3 = fmaf(w3[j * 9 + 3], v1[j], d3);
                    d3 = fmaf(w3[j * 9 + 4], q1v[j], d3);
                    d3 = fmaf(w3[j * 9 + 5], r1[j], d3);
                    d3 = fmaf(w3[j * 9 + 6], v2[j], d3);
                    d3 = fmaf(w3[j * 9 + 7], q2v[j], d3);
                    d3 = fmaf(w3[j * 9 + 8], r2[j], d3);
                }
                if (stv) {
                    int gy = by0 + qy - 1;
                    bool ok = colOK && ((unsigned)gy < 256u);
                    dst3[qy * 18 + lane] = ok ? d3 : 0.0f;
                }
                if (qy >= 1 && qy <= 8) {
                    float d1 = bias1;
#pragma unroll
                    for (int j = 0; j < 3; ++j) {
                        d1 = fmaf(w1[j * 9 + 0], v0[j], d1);
                        d1 = fmaf(w1[j * 9 + 1], q0v[j], d1);
                        d1 = fmaf(w1[j * 9 + 2], r0[j], d1);
                        d1 = fmaf(w1[j * 9 + 3], v1[j], d1);
                        d1 = fmaf(w1[j * 9 + 4], q1v[j], d1);
                        d1 = fmaf(w1[j * 9 + 5], r1[j], d1);
                        d1 = fmaf(w1[j * 9 + 6], v2[j], d1);
                        d1 = fmaf(w1[j * 9 + 7], q2v[j], d1);
                        d1 = fmaf(w1[j * 9 + 8], r2[j], d1);
                    }
                    if (st1) dst1[(qy - 1) * 16 + lane - 1] = d1;
                }
#pragma unroll
                for (int j = 0; j < 3; ++j) {
                    v0[j] = v1[j]; q0v[j] = q1v[j]; r0[j] = r1[j];
                    v1[j] = v2[j]; q1v[j] = q2v[j]; r1[j] = r2[j];
                }
            }
        }
        __syncthreads();   // D1 + D3A ready

        if (gh == 0) {
            // ---- gating + packed proj (o 0..31) from D1 ----
#pragma unroll
            for (int cpl = 0; cpl < 4; ++cpl) {
                float d1a = sm[SM_D1 + (cpl * 2 + 0) * 128 + tA];
                float d1b = sm[SM_D1 + (cpl * 2 + 1) * 128 + tA];
                float g1 = gelu_exact(d1a) * d1b;
                u64 g1p = pk2(g1, g1);
                const ulonglong2* wo = (const ulonglong2*)(sm + SM_GWOUT + cpl * 64);
#pragma unroll
                for (int mm = 0; mm < 8; ++mm) {
                    ulonglong2 w2 = wo[mm];
                    fma2(acc[2 * mm], w2.x, g1p);
                    fma2(acc[2 * mm + 1], w2.y, g1p);
                }
            }
        } else {
            // ---- B3 + packed proj (o 32..63) ----
#pragma unroll
            for (int cpl = 0; cpl < 4; ++cpl) {
                const int cp = 4 * g + cpl;
                float wA[12], wB[12];
#pragma unroll
                for (int i = 0; i < 3; ++i) {
                    float4 w4 = ((const float4*)(sm + SM_GDW3B + (cpl * 2) * 12))[i];
                    wA[4 * i] = w4.x; wA[4 * i + 1] = w4.y;
                    wA[4 * i + 2] = w4.z; wA[4 * i + 3] = w4.w;
                    float4 v4 = ((const float4*)(sm + SM_GDW3B + (cpl * 2 + 1) * 12))[i];
                    wB[4 * i] = v4.x; wB[4 * i + 1] = v4.y;
                    wB[4 * i + 2] = v4.z; wB[4 * i + 3] = v4.w;
                }
                float dA = sm[SM_BDW3B + cp];
                float dB = sm[SM_BDW3B + cp + 64];
                const float* dz = sm + SM_D3A + cpl * 360;
#pragma unroll
                for (int ky = 0; ky < 3; ++ky)
#pragma unroll
                    for (int kx = 0; kx < 3; ++kx) {
                        int qi = (tyl + ky) * 18 + (tx + kx);
                        int t = ky * 3 + kx;
                        dA = fmaf(wA[t], dz[qi], dA);
                        dB = fmaf(wB[t], dz[180 + qi], dB);
                    }
                float g2 = gelu_exact(dA) * dB;
                u64 g2p = pk2(g2, g2);
                const ulonglong2* wo = (const ulonglong2*)(sm + SM_GWOUT + cpl * 64 + 32);
#pragma unroll
                for (int mm = 0; mm < 8; ++mm) {
                    ulonglong2 w2 = wo[mm];
                    fma2(acc[2 * mm], w2.x, g2p);
                    fma2(acc[2 * mm + 1], w2.y, g2p);
                }
            }
        }
        __syncthreads();   // protect WT/GDW*/XC/D1/D3A before next staging
    }

    float* ob = out + (size_t)b * 64 * 65536 + (size_t)(by0 + tyl) * 256 + (bx0 + tx);
    const int o0 = gh * 32;
#pragma unroll
    for (int mm = 0; mm < 16; ++mm) {
        float lo, hi;
        upk2(acc[mm], lo, hi);
        ob[(size_t)(o0 + 2 * mm) * 65536]     = lo + sm[SM_BOUT + o0 + 2 * mm];
        ob[(size_t)(o0 + 2 * mm + 1) * 65536] = hi + sm[SM_BOUT + o0 + 2 * mm + 1];
    }
}

extern "C" void kernel_launch(void* const* d_in, const int* in_sizes, int n_in,
                              void* d_out, int out_size)
{
    (void)in_sizes; (void)n_in; (void)out_size;
    const float* x      = (const float*)d_in[0];
    const float* pneff  = (const float*)d_in[1];
    const float* w_in   = (const float*)d_in[2];
    const float* b_in   = (const float*)d_in[3];
    const float* w_pn   = (const float*)d_in[4];
    const float* b_pn   = (const float*)d_in[5];
    const float* w_dw1  = (const float*)d_in[6];
    const float* b_dw1  = (const float*)d_in[7];
    const float* w_dw3a = (const float*)d_in[8];
    const float* b_dw3a = (const float*)d_in[9];
    const float* w_dw3b = (const float*)d_in[10];
    const float* b_dw3b = (const float*)d_in[11];
    const float* w_out  = (const float*)d_in[12];
    const float* b_out  = (const float*)d_in[13];
    float* out = (float*)d_out;

    const size_t smem_bytes = SM_TOTAL * sizeof(float);
    cudaFuncSetAttribute(ffn_fused_kernel,
                         cudaFuncAttributeMaxDynamicSharedMemorySize,
                         (int)smem_bytes);
    dim3 grid(16, 32, 4);
    ffn_fused_kernel<<<grid, 256, smem_bytes>>>(
        x, pneff, w_in, b_in, w_pn, b_pn, w_dw1, b_dw1,
        w_dw3a, b_dw3a, w_dw3b, b_dw3b, w_out, b_out, out);
}

// round 15
// speedup vs baseline: 1.7908x; 1.1507x over previous
#include <cuda_runtime.h>
#include <math.h>

typedef unsigned long long u64;

// Round 15: R14 merge (B1+B2 share one sliding window) restructured
// channel-outer to eliminate the register spills that sank R14.

#define HALO   240     // 20 x 12
#define SM_SX     0        // 64*240 = 15360
#define SM_SPN    15360    // 480
#define SM_XC     15840    // 5760
#define SM_D3A    21600    // 1440
#define SM_D1     23040    // 1024
#define SM_WT     24064    // 1536
#define SM_GDW1   25600    // 8*28 = 224
#define SM_GDW3A  25824    // 224
#define SM_GDW3B  26048    // 96
#define SM_GWOUT  26144    // 256
#define SM_BDW1   26400    // 128
#define SM_BDW3A  26528    // 128
#define SM_BDW3B  26656    // 128
#define SM_BOUT   26784    // 64
#define SM_WPN    26848    // 256
#define SM_BPN    27104    // 128
#define SM_BIN    27232    // 256
#define SM_TOTAL  27488    // 109952 bytes -> 2 blocks/SM

__device__ __forceinline__ u64 pk2(float lo, float hi) {
    u64 r; asm("mov.b64 %0,{%1,%2};" : "=l"(r) : "f"(lo), "f"(hi)); return r;
}
__device__ __forceinline__ void upk2(u64 v, float& lo, float& hi) {
    asm("mov.b64 {%0,%1},%2;" : "=f"(lo), "=f"(hi) : "l"(v));
}
__device__ __forceinline__ void fma2(u64& d, u64 a, u64 b) {
    asm("fma.rn.f32x2 %0,%1,%2,%0;" : "+l"(d) : "l"(a), "l"(b));
}
__device__ __forceinline__ u64 lds64(const float* p) { return *(const u64*)p; }

__device__ __forceinline__ float gelu_exact(float v) {
    return 0.5f * v * (1.0f + erff(v * 0.70710678118654752f));
}

// Phase A, B-half (12 xi channels, 6 pairs) for adjacent pixels p0, p0+1.
__device__ __forceinline__ void phaseA_B(float* sm, int g, int p0,
                                         float m0, float m1)
{
    u64 a0[6], a1[6];
#pragma unroll
    for (int j = 0; j < 6; ++j) {
        u64 bp = lds64(sm + SM_BIN + 64 + 12 * g + 2 * j);
        a0[j] = bp; a1[j] = bp;
    }
#pragma unroll 4
    for (int k = 0; k < 64; ++k) {
        float2 s = *(const float2*)(sm + SM_SX + k * 240 + p0);
        u64 s0 = pk2(s.x, s.x);
        u64 s1 = pk2(s.y, s.y);
        const float* wt = sm + SM_WT + k * 24;
        ulonglong2 w01 = *(const ulonglong2*)(wt);
        ulonglong2 w23 = *(const ulonglong2*)(wt + 4);
        ulonglong2 w45 = *(const ulonglong2*)(wt + 8);
        fma2(a0[0], w01.x, s0); fma2(a1[0], w01.x, s1);
        fma2(a0[1], w01.y, s0); fma2(a1[1], w01.y, s1);
        fma2(a0[2], w23.x, s0); fma2(a1[2], w23.x, s1);
        fma2(a0[3], w23.y, s0); fma2(a1[3], w23.y, s1);
        fma2(a0[4], w45.x, s0); fma2(a1[4], w45.x, s1);
        fma2(a0[5], w45.y, s0); fma2(a1[5], w45.y, s1);
    }
#pragma unroll
    for (int j = 0; j < 6; ++j) {
        float lo0, hi0, lo1, hi1;
        upk2(a0[j], lo0, hi0);
        upk2(a1[j], lo1, hi1);
        float* c0 = sm + SM_XC + (12 + 2 * j) * 240 + p0;
        float* c1 = sm + SM_XC + (13 + 2 * j) * 240 + p0;
        c0[0] = lo0 * m0; c0[1] = lo1 * m1;
        c1[0] = hi0 * m0; c1[1] = hi1 * m1;
    }
}

// Phase A, A-half. NP = xi channel pairs {0, 2, 6}.
template<int NP>
__device__ __forceinline__ void phaseA_A(float* sm, int g, int p0,
                                         float m0, float m1,
                                         float pn00, float pn01,
                                         float pn10, float pn11)
{
    float xv0[12], xv1[12];
    if (NP > 0) {
        u64 a0[NP > 0 ? NP : 1], a1[NP > 0 ? NP : 1];
        const int base = (NP == 2) ? 0 : (12 * g - 128);
#pragma unroll
        for (int j = 0; j < NP; ++j) {
            u64 bp = lds64(sm + SM_BIN + base + 2 * j);
            a0[j] = bp; a1[j] = bp;
        }
#pragma unroll 4
        for (int k = 0; k < 64; ++k) {
            float2 s = *(const float2*)(sm + SM_SX + k * 240 + p0);
            u64 s0 = pk2(s.x, s.x);
            u64 s1 = pk2(s.y, s.y);
            const float* wt = sm + SM_WT + k * 24 + 12;
            if (NP == 2) {
                ulonglong2 w = *(const ulonglong2*)(wt);
                fma2(a0[0], w.x, s0); fma2(a1[0], w.x, s1);
                fma2(a0[1], w.y, s0); fma2(a1[1], w.y, s1);
            } else {
                ulonglong2 w01 = *(const ulonglong2*)(wt);
                ulonglong2 w23 = *(const ulonglong2*)(wt + 4);
                ulonglong2 w45 = *(const ulonglong2*)(wt + 8);
                fma2(a0[0], w01.x, s0); fma2(a1[0], w01.x, s1);
                fma2(a0[1], w01.y, s0); fma2(a1[1], w01.y, s1);
                fma2(a0[2], w23.x, s0); fma2(a1[2], w23.x, s1);
                fma2(a0[3], w23.y, s0); fma2(a1[3], w23.y, s1);
                fma2(a0[4], w45.x, s0); fma2(a1[4], w45.x, s1);
                fma2(a0[5], w45.y, s0); fma2(a1[5], w45.y, s1);
            }
        }
        const int s0i = (NP == 2) ? 8 : 0;
#pragma unroll
        for (int j = 0; j < NP; ++j) {
            upk2(a0[j], xv0[s0i + 2 * j], xv0[s0i + 2 * j + 1]);
            upk2(a1[j], xv1[s0i + 2 * j], xv1[s0i + 2 * j + 1]);
        }
    }
#pragma unroll
    for (int s = 0; s < 12; ++s) {
        const bool isPN = (NP == 0) || (NP == 2 && s < 8);
        if (isPN) {
            int c = 12 * g + s;
            float w0 = sm[SM_WPN + 2 * c], w1 = sm[SM_WPN + 2 * c + 1];
            float bb = sm[SM_BPN + c];
            xv0[s] = fmaf(w0, pn00, fmaf(w1, pn10, bb));
            xv1[s] = fmaf(w0, pn01, fmaf(w1, pn11, bb));
        }
        float* cp = sm + SM_XC + s * 240 + p0;
        cp[0] = xv0[s] * m0;
        cp[1] = xv1[s] * m1;
    }
}

__global__ void __launch_bounds__(256, 2)
ffn_fused_kernel(const float* __restrict__ x,
                 const float* __restrict__ pneff,
                 const float* __restrict__ w_in,  const float* __restrict__ b_in,
                 const float* __restrict__ w_pn,  const float* __restrict__ b_pn,
                 const float* __restrict__ w_dw1, const float* __restrict__ b_dw1,
                 const float* __restrict__ w_dw3a,const float* __restrict__ b_dw3a,
                 const float* __restrict__ w_dw3b,const float* __restrict__ b_dw3b,
                 const float* __restrict__ w_out, const float* __restrict__ b_out,
                 float* __restrict__ out)
{
    extern __shared__ float sm[];
    const int tid = threadIdx.x;
    const int bx0 = blockIdx.x * 16;
    const int by0 = blockIdx.y * 8;
    const int b   = blockIdx.z;

    if (tid < 128) {
        sm[SM_BDW1 + tid]  = b_dw1[tid];
        sm[SM_BDW3A + tid] = b_dw3a[tid];
        sm[SM_BDW3B + tid] = b_dw3b[tid];
        sm[SM_BPN + tid]   = b_pn[tid];
    }
    if (tid < 64) sm[SM_BOUT + tid] = b_out[tid];
    sm[SM_WPN + tid] = w_pn[tid];
    sm[SM_BIN + tid] = b_in[tid];

    {
        const float* xb = x + (size_t)b * 64 * 65536;
        for (int v = tid; v < 64 * HALO; v += 256) {
            int c = v / HALO, p = v - c * HALO;
            int ry = p / 20, rx = p - ry * 20;
            int gy = by0 + ry - 2, gx = bx0 + rx - 2;
            float vv = 0.0f;
            if ((unsigned)gy < 256u && (unsigned)gx < 256u)
                vv = xb[(size_t)c * 65536 + gy * 256 + gx];
            sm[SM_SX + c * HALO + p] = vv;
        }
        const float* pnb = pneff + (size_t)b * 2 * 65536;
        for (int v = tid; v < 2 * HALO; v += 256) {
            int c = v / HALO, p = v - c * HALO;
            int ry = p / 20, rx = p - ry * 20;
            int gy = by0 + ry - 2, gx = bx0 + rx - 2;
            float vv = 0.0f;
            if ((unsigned)gy < 256u && (unsigned)gx < 256u)
                vv = pnb[(size_t)c * 65536 + gy * 256 + gx];
            sm[SM_SPN + c * HALO + p] = vv;
        }
    }
    __syncthreads();

    const int tA  = tid & 127;
    const int gh  = tid >> 7;
    const bool doA = (tA < 120);
    const int p0  = doA ? (2 * tA) : 0;
    float m0, m1;
    {
        int ry = p0 / 20, rx = p0 - ry * 20;
        m0 = ((unsigned)(by0 + ry - 2) < 256u && (unsigned)(bx0 + rx - 2) < 256u) ? 1.f : 0.f;
        int p1 = p0 + 1;
        int ry1 = p1 / 20, rx1 = p1 - ry1 * 20;
        m1 = ((unsigned)(by0 + ry1 - 2) < 256u && (unsigned)(bx0 + rx1 - 2) < 256u) ? 1.f : 0.f;
    }
    const float pn00 = sm[SM_SPN + p0],        pn01 = sm[SM_SPN + p0 + 1];
    const float pn10 = sm[SM_SPN + HALO + p0], pn11 = sm[SM_SPN + HALO + p0 + 1];

    const int tyl  = tA >> 4;
    const int tx   = tA & 15;
    const int warp = tid >> 5;
    const int lane = tid & 31;

    u64 acc[16];
#pragma unroll
    for (int i = 0; i < 16; ++i) acc[i] = 0ULL;

    for (int g = 0; g < 16; ++g) {
        // ---- stage per-group weights ----
        {
            const int nw = (g < 10) ? 768 : (g == 10 ? 1024 : 1536);
            const int ncol = nw / 64;
            for (int v = tid; v < nw; v += 256) {
                int k = v / ncol, j = v - k * ncol;
                int xi = (j < 12) ? (64 + 12 * g + j)
                                  : ((g == 10) ? (j - 12) : (12 * g - 128 + j - 12));
                sm[SM_WT + k * 24 + j] = w_in[xi * 64 + k];
            }
            for (int v = tid; v < 216; v += 256) {
                int cc = v / 27, t = v - cc * 27;
                int ch = 4 * g + (cc >> 1) + (cc & 1) * 64;
                sm[SM_GDW1 + cc * 28 + t]  = w_dw1[ch * 27 + t];
                sm[SM_GDW3A + cc * 28 + t] = w_dw3a[ch * 27 + t];
            }
            if (tid < 72) {
                int cc = tid / 9, t = tid - cc * 9;
                int ch = 4 * g + (cc >> 1) + (cc & 1) * 64;
                sm[SM_GDW3B + cc * 12 + t] = w_dw3b[ch * 9 + t];
            }
            {
                int cpl = tid >> 6, o = tid & 63;
                sm[SM_GWOUT + tid] = w_out[o * 64 + 4 * g + cpl];
            }
        }
        __syncthreads();   // weights ready

        // ---- Phase A (channel-split, packed pairs) ----
        if (gh == 0) {
            if (doA) phaseA_B(sm, g, p0, m0, m1);
        } else if (doA) {
            if (g < 10)       phaseA_A<0>(sm, g, p0, m0, m1, pn00, pn01, pn10, pn11);
            else if (g == 10) phaseA_A<2>(sm, g, p0, m0, m1, pn00, pn01, pn10, pn11);
            else              phaseA_A<6>(sm, g, p0, m0, m1, pn00, pn01, pn10, pn11);
        }
        __syncthreads();   // XC ready

        // ---- Merged B1+B2, channel-outer (low register pressure) ----
        {
            const int cpl = warp >> 1, h = warp & 1;
            const int cc = cpl * 2 + h;
            const int cp = 4 * g + cpl;
            const bool ld = (lane < 20);

            float d3r[10], d1r[8];
            {
                const float bias3 = sm[SM_BDW3A + cp + h * 64];
                const float bias1 = sm[SM_BDW1 + cp + h * 64];
#pragma unroll
                for (int qy = 0; qy < 10; ++qy) d3r[qy] = bias3;
#pragma unroll
                for (int r = 0; r < 8; ++r) d1r[r] = bias1;
            }

#pragma unroll
            for (int j = 0; j < 3; ++j) {
                float w3r[9], w1r[9];
#pragma unroll
                for (int t = 0; t < 9; ++t) {
                    w3r[t] = sm[SM_GDW3A + cc * 28 + j * 9 + t];
                    w1r[t] = sm[SM_GDW1 + cc * 28 + j * 9 + t];
                }
                const float* xc = sm + SM_XC + (h * 12 + 3 * cpl + j) * 240;
                float v0, q0, r0, v1, q1, r1, v2, q2, r2;
                {
                    float a = ld ? xc[lane] : 0.0f;
                    v0 = a;
                    q0 = __shfl_down_sync(0xffffffffu, a, 1);
                    r0 = __shfl_down_sync(0xffffffffu, a, 2);
                    float bva = ld ? xc[20 + lane] : 0.0f;
                    v1 = bva;
                    q1 = __shfl_down_sync(0xffffffffu, bva, 1);
                    r1 = __shfl_down_sync(0xffffffffu, bva, 2);
                }
#pragma unroll
                for (int qy = 0; qy < 10; ++qy) {
                    float c = ld ? xc[(qy + 2) * 20 + lane] : 0.0f;
                    v2 = c;
                    q2 = __shfl_down_sync(0xffffffffu, c, 1);
                    r2 = __shfl_down_sync(0xffffffffu, c, 2);

                    float d3 = d3r[qy];
                    d3 = fmaf(w3r[0], v0, d3);
                    d3 = fmaf(w3r[1], q0, d3);
                    d3 = fmaf(w3r[2], r0, d3);
                    d3 = fmaf(w3r[3], v1, d3);
                    d3 = fmaf(w3r[4], q1, d3);
                    d3 = fmaf(w3r[5], r1, d3);
                    d3 = fmaf(w3r[6], v2, d3);
                    d3 = fmaf(w3r[7], q2, d3);
                    d3 = fmaf(w3r[8], r2, d3);
                    d3r[qy] = d3;

                    if (qy >= 1 && qy <= 8) {
                        float d1 = d1r[qy - 1];
                        d1 = fmaf(w1r[0], v0, d1);
                        d1 = fmaf(w1r[1], q0, d1);
                        d1 = fmaf(w1r[2], r0, d1);
                        d1 = fmaf(w1r[3], v1, d1);
                        d1 = fmaf(w1r[4], q1, d1);
                        d1 = fmaf(w1r[5], r1, d1);
                        d1 = fmaf(w1r[6], v2, d1);
                        d1 = fmaf(w1r[7], q2, d1);
                        d1 = fmaf(w1r[8], r2, d1);
                        d1r[qy - 1] = d1;
                    }
                    v0 = v1; q0 = q1; r0 = r1;
                    v1 = v2; q1 = q2; r1 = r2;
                }
            }

            // stores
            {
                const bool stv = (lane < 18);
                const bool st1 = (lane >= 1 && lane <= 16);
                const int gxc  = bx0 + lane - 1;
                const bool colOK = stv && ((unsigned)gxc < 256u);
                float* dst3 = sm + SM_D3A + cpl * 360 + h * 180;
                float* dst1 = sm + SM_D1 + cc * 128;
#pragma unroll
                for (int qy = 0; qy < 10; ++qy) {
                    if (stv) {
                        int gy = by0 + qy - 1;
                        bool ok = colOK && ((unsigned)gy < 256u);
                        dst3[qy * 18 + lane] = ok ? d3r[qy] : 0.0f;
                    }
                }
                if (st1) {
#pragma unroll
                    for (int r = 0; r < 8; ++r)
                        dst1[r * 16 + lane - 1] = d1r[r];
                }
            }
        }
        __syncthreads();   // D1 + D3A ready

        if (gh == 0) {
            // ---- gating + packed proj (o 0..31) from D1 ----
#pragma unroll
            for (int cpl = 0; cpl < 4; ++cpl) {
                float d1a = sm[SM_D1 + (cpl * 2 + 0) * 128 + tA];
                float d1b = sm[SM_D1 + (cpl * 2 + 1) * 128 + tA];
                float g1 = gelu_exact(d1a) * d1b;
                u64 g1p = pk2(g1, g1);
                const ulonglong2* wo = (const ulonglong2*)(sm + SM_GWOUT + cpl * 64);
#pragma unroll
                for (int mm = 0; mm < 8; ++mm) {
                    ulonglong2 w2 = wo[mm];
                    fma2(acc[2 * mm], w2.x, g1p);
                    fma2(acc[2 * mm + 1], w2.y, g1p);
                }
            }
        } else {
            // ---- B3 + packed proj (o 32..63) ----
#pragma unroll
            for (int cpl = 0; cpl < 4; ++cpl) {
                const int cp = 4 * g + cpl;
                float wA[12], wB[12];
#pragma unroll
                for (int i = 0; i < 3; ++i) {
                    float4 w4 = ((const float4*)(sm + SM_GDW3B + (cpl * 2) * 12))[i];
                    wA[4 * i] = w4.x; wA[4 * i + 1] = w4.y;
                    wA[4 * i + 2] = w4.z; wA[4 * i + 3] = w4.w;
                    float4 v4 = ((const float4*)(sm + SM_GDW3B + (cpl * 2 + 1) * 12))[i];
                    wB[4 * i] = v4.x; wB[4 * i + 1] = v4.y;
                    wB[4 * i + 2] = v4.z; wB[4 * i + 3] = v4.w;
                }
                float dA = sm[SM_BDW3B + cp];
                float dB = sm[SM_BDW3B + cp + 64];
                const float* dz = sm + SM_D3A + cpl * 360;
#pragma unroll
                for (int ky = 0; ky < 3; ++ky)
#pragma unroll
                    for (int kx = 0; kx < 3; ++kx) {
                        int qi = (tyl + ky) * 18 + (tx + kx);
                        int t = ky * 3 + kx;
                        dA = fmaf(wA[t], dz[qi], dA);
                        dB = fmaf(wB[t], dz[180 + qi], dB);
                    }
                float g2 = gelu_exact(dA) * dB;
                u64 g2p = pk2(g2, g2);
                const ulonglong2* wo = (const ulonglong2*)(sm + SM_GWOUT + cpl * 64 + 32);
#pragma unroll
                for (int mm = 0; mm < 8; ++mm) {
                    ulonglong2 w2 = wo[mm];
                    fma2(acc[2 * mm], w2.x, g2p);
                    fma2(acc[2 * mm + 1], w2.y, g2p);
                }
            }
        }
        __syncthreads();   // protect WT/GDW*/XC/D1/D3A before next staging
    }

    float* ob = out + (size_t)b * 64 * 65536 + (size_t)(by0 + tyl) * 256 + (bx0 + tx);
    const int o0 = gh * 32;
#pragma unroll
    for (int mm = 0; mm < 16; ++mm) {
        float lo, hi;
        upk2(acc[mm], lo, hi);
        ob[(size_t)(o0 + 2 * mm) * 65536]     = lo + sm[SM_BOUT + o0 + 2 * mm];
        ob[(size_t)(o0 + 2 * mm + 1) * 65536] = hi + sm[SM_BOUT + o0 + 2 * mm + 1];
    }
}

extern "C" void kernel_launch(void* const* d_in, const int* in_sizes, int n_in,
                              void* d_out, int out_size)
{
    (void)in_sizes; (void)n_in; (void)out_size;
    const float* x      = (const float*)d_in[0];
    const float* pneff  = (const float*)d_in[1];
    const float* w_in   = (const float*)d_in[2];
    const float* b_in   = (const float*)d_in[3];
    const float* w_pn   = (const float*)d_in[4];
    const float* b_pn   = (const float*)d_in[5];
    const float* w_dw1  = (const float*)d_in[6];
    const float* b_dw1  = (const float*)d_in[7];
    const float* w_dw3a = (const float*)d_in[8];
    const float* b_dw3a = (const float*)d_in[9];
    const float* w_dw3b = (const float*)d_in[10];
    const float* b_dw3b = (const float*)d_in[11];
    const float* w_out  = (const float*)d_in[12];
    const float* b_out  = (const float*)d_in[13];
    float* out = (float*)d_out;

    const size_t smem_bytes = SM_TOTAL * sizeof(float);
    cudaFuncSetAttribute(ffn_fused_kernel,
                         cudaFuncAttributeMaxDynamicSharedMemorySize,
                         (int)smem_bytes);
    dim3 grid(16, 32, 4);
    ffn_fused_kernel<<<grid, 256, smem_bytes>>>(
        x, pneff, w_in, b_in, w_pn, b_pn, w_dw1, b_dw1,
        w_dw3a, b_dw3a, w_dw3b, b_dw3b, w_out, b_out, out);
}

// round 16
// speedup vs baseline: 1.9509x; 1.0894x over previous
#include <cuda_runtime.h>
#include <math.h>

typedef unsigned long long u64;

// Round 16: R15 base + (1) {d3,d1} f32x2-paired merged window pass,
// (2) B3 computed in-register from masked d3 (D3A smem round-trip deleted).

#define HALO   240     // 20 x 12
#define SM_SX     0        // 64*240 = 15360
#define SM_SPN    15360    // 480
#define SM_XC     15840    // 5760
#define SM_D3B    21600    // 8*128 = 1024 (B3 results)
#define SM_D1     22624    // 8*128 = 1024
#define SM_WT     23648    // 1536
#define SM_GDW31  25184    // 8 cc * 56 (27 {dw3a,dw1} pairs, padded)
#define SM_GDW3B  25632    // 8*12 = 96
#define SM_GWOUT  25728    // 256
#define SM_BDW1   25984    // 128
#define SM_BDW3A  26112    // 128
#define SM_BDW3B  26240    // 128
#define SM_BOUT   26368    // 64
#define SM_WPN    26432    // 256
#define SM_BPN    26688    // 128
#define SM_BIN    26816    // 256
#define SM_TOTAL  27072    // 108288 bytes -> 2 blocks/SM

__device__ __forceinline__ u64 pk2(float lo, float hi) {
    u64 r; asm("mov.b64 %0,{%1,%2};" : "=l"(r) : "f"(lo), "f"(hi)); return r;
}
__device__ __forceinline__ void upk2(u64 v, float& lo, float& hi) {
    asm("mov.b64 {%0,%1},%2;" : "=f"(lo), "=f"(hi) : "l"(v));
}
__device__ __forceinline__ void fma2(u64& d, u64 a, u64 b) {
    asm("fma.rn.f32x2 %0,%1,%2,%0;" : "+l"(d) : "l"(a), "l"(b));
}
__device__ __forceinline__ u64 lds64(const float* p) { return *(const u64*)p; }

__device__ __forceinline__ float gelu_exact(float v) {
    return 0.5f * v * (1.0f + erff(v * 0.70710678118654752f));
}

// Phase A, B-half (12 xi channels, 6 pairs) for adjacent pixels p0, p0+1.
__device__ __forceinline__ void phaseA_B(float* sm, int g, int p0,
                                         float m0, float m1)
{
    u64 a0[6], a1[6];
#pragma unroll
    for (int j = 0; j < 6; ++j) {
        u64 bp = lds64(sm + SM_BIN + 64 + 12 * g + 2 * j);
        a0[j] = bp; a1[j] = bp;
    }
#pragma unroll 4
    for (int k = 0; k < 64; ++k) {
        float2 s = *(const float2*)(sm + SM_SX + k * 240 + p0);
        u64 s0 = pk2(s.x, s.x);
        u64 s1 = pk2(s.y, s.y);
        const float* wt = sm + SM_WT + k * 24;
        ulonglong2 w01 = *(const ulonglong2*)(wt);
        ulonglong2 w23 = *(const ulonglong2*)(wt + 4);
        ulonglong2 w45 = *(const ulonglong2*)(wt + 8);
        fma2(a0[0], w01.x, s0); fma2(a1[0], w01.x, s1);
        fma2(a0[1], w01.y, s0); fma2(a1[1], w01.y, s1);
        fma2(a0[2], w23.x, s0); fma2(a1[2], w23.x, s1);
        fma2(a0[3], w23.y, s0); fma2(a1[3], w23.y, s1);
        fma2(a0[4], w45.x, s0); fma2(a1[4], w45.x, s1);
        fma2(a0[5], w45.y, s0); fma2(a1[5], w45.y, s1);
    }
#pragma unroll
    for (int j = 0; j < 6; ++j) {
        float lo0, hi0, lo1, hi1;
        upk2(a0[j], lo0, hi0);
        upk2(a1[j], lo1, hi1);
        float* c0 = sm + SM_XC + (12 + 2 * j) * 240 + p0;
        float* c1 = sm + SM_XC + (13 + 2 * j) * 240 + p0;
        c0[0] = lo0 * m0; c0[1] = lo1 * m1;
        c1[0] = hi0 * m0; c1[1] = hi1 * m1;
    }
}

// Phase A, A-half. NP = xi channel pairs {0, 2, 6}.
template<int NP>
__device__ __forceinline__ void phaseA_A(float* sm, int g, int p0,
                                         float m0, float m1,
                                         float pn00, float pn01,
                                         float pn10, float pn11)
{
    float xv0[12], xv1[12];
    if (NP > 0) {
        u64 a0[NP > 0 ? NP : 1], a1[NP > 0 ? NP : 1];
        const int base = (NP == 2) ? 0 : (12 * g - 128);
#pragma unroll
        for (int j = 0; j < NP; ++j) {
            u64 bp = lds64(sm + SM_BIN + base + 2 * j);
            a0[j] = bp; a1[j] = bp;
        }
#pragma unroll 4
        for (int k = 0; k < 64; ++k) {
            float2 s = *(const float2*)(sm + SM_SX + k * 240 + p0);
            u64 s0 = pk2(s.x, s.x);
            u64 s1 = pk2(s.y, s.y);
            const float* wt = sm + SM_WT + k * 24 + 12;
            if (NP == 2) {
                ulonglong2 w = *(const ulonglong2*)(wt);
                fma2(a0[0], w.x, s0); fma2(a1[0], w.x, s1);
                fma2(a0[1], w.y, s0); fma2(a1[1], w.y, s1);
            } else {
                ulonglong2 w01 = *(const ulonglong2*)(wt);
                ulonglong2 w23 = *(const ulonglong2*)(wt + 4);
                ulonglong2 w45 = *(const ulonglong2*)(wt + 8);
                fma2(a0[0], w01.x, s0); fma2(a1[0], w01.x, s1);
                fma2(a0[1], w01.y, s0); fma2(a1[1], w01.y, s1);
                fma2(a0[2], w23.x, s0); fma2(a1[2], w23.x, s1);
                fma2(a0[3], w23.y, s0); fma2(a1[3], w23.y, s1);
                fma2(a0[4], w45.x, s0); fma2(a1[4], w45.x, s1);
                fma2(a0[5], w45.y, s0); fma2(a1[5], w45.y, s1);
            }
        }
        const int s0i = (NP == 2) ? 8 : 0;
#pragma unroll
        for (int j = 0; j < NP; ++j) {
            upk2(a0[j], xv0[s0i + 2 * j], xv0[s0i + 2 * j + 1]);
            upk2(a1[j], xv1[s0i + 2 * j], xv1[s0i + 2 * j + 1]);
        }
    }
#pragma unroll
    for (int s = 0; s < 12; ++s) {
        const bool isPN = (NP == 0) || (NP == 2 && s < 8);
        if (isPN) {
            int c = 12 * g + s;
            float w0 = sm[SM_WPN + 2 * c], w1 = sm[SM_WPN + 2 * c + 1];
            float bb = sm[SM_BPN + c];
            xv0[s] = fmaf(w0, pn00, fmaf(w1, pn10, bb));
            xv1[s] = fmaf(w0, pn01, fmaf(w1, pn11, bb));
        }
        float* cp = sm + SM_XC + s * 240 + p0;
        cp[0] = xv0[s] * m0;
        cp[1] = xv1[s] * m1;
    }
}

__global__ void __launch_bounds__(256, 2)
ffn_fused_kernel(const float* __restrict__ x,
                 const float* __restrict__ pneff,
                 const float* __restrict__ w_in,  const float* __restrict__ b_in,
                 const float* __restrict__ w_pn,  const float* __restrict__ b_pn,
                 const float* __restrict__ w_dw1, const float* __restrict__ b_dw1,
                 const float* __restrict__ w_dw3a,const float* __restrict__ b_dw3a,
                 const float* __restrict__ w_dw3b,const float* __restrict__ b_dw3b,
                 const float* __restrict__ w_out, const float* __restrict__ b_out,
                 float* __restrict__ out)
{
    extern __shared__ float sm[];
    const int tid = threadIdx.x;
    const int bx0 = blockIdx.x * 16;
    const int by0 = blockIdx.y * 8;
    const int b   = blockIdx.z;

    if (tid < 128) {
        sm[SM_BDW1 + tid]  = b_dw1[tid];
        sm[SM_BDW3A + tid] = b_dw3a[tid];
        sm[SM_BDW3B + tid] = b_dw3b[tid];
        sm[SM_BPN + tid]   = b_pn[tid];
    }
    if (tid < 64) sm[SM_BOUT + tid] = b_out[tid];
    sm[SM_WPN + tid] = w_pn[tid];
    sm[SM_BIN + tid] = b_in[tid];

    {
        const float* xb = x + (size_t)b * 64 * 65536;
        for (int v = tid; v < 64 * HALO; v += 256) {
            int c = v / HALO, p = v - c * HALO;
            int ry = p / 20, rx = p - ry * 20;
            int gy = by0 + ry - 2, gx = bx0 + rx - 2;
            float vv = 0.0f;
            if ((unsigned)gy < 256u && (unsigned)gx < 256u)
                vv = xb[(size_t)c * 65536 + gy * 256 + gx];
            sm[SM_SX + c * HALO + p] = vv;
        }
        const float* pnb = pneff + (size_t)b * 2 * 65536;
        for (int v = tid; v < 2 * HALO; v += 256) {
            int c = v / HALO, p = v - c * HALO;
            int ry = p / 20, rx = p - ry * 20;
            int gy = by0 + ry - 2, gx = bx0 + rx - 2;
            float vv = 0.0f;
            if ((unsigned)gy < 256u && (unsigned)gx < 256u)
                vv = pnb[(size_t)c * 65536 + gy * 256 + gx];
            sm[SM_SPN + c * HALO + p] = vv;
        }
    }
    __syncthreads();

    const int tA  = tid & 127;
    const int gh  = tid >> 7;
    const bool doA = (tA < 120);
    const int p0  = doA ? (2 * tA) : 0;
    float m0, m1;
    {
        int ry = p0 / 20, rx = p0 - ry * 20;
        m0 = ((unsigned)(by0 + ry - 2) < 256u && (unsigned)(bx0 + rx - 2) < 256u) ? 1.f : 0.f;
        int p1 = p0 + 1;
        int ry1 = p1 / 20, rx1 = p1 - ry1 * 20;
        m1 = ((unsigned)(by0 + ry1 - 2) < 256u && (unsigned)(bx0 + rx1 - 2) < 256u) ? 1.f : 0.f;
    }
    const float pn00 = sm[SM_SPN + p0],        pn01 = sm[SM_SPN + p0 + 1];
    const float pn10 = sm[SM_SPN + HALO + p0], pn11 = sm[SM_SPN + HALO + p0 + 1];

    const int tyl  = tA >> 4;
    const int tx   = tA & 15;
    const int warp = tid >> 5;
    const int lane = tid & 31;

    u64 acc[16];
#pragma unroll
    for (int i = 0; i < 16; ++i) acc[i] = 0ULL;

    for (int g = 0; g < 16; ++g) {
        // ---- stage per-group weights ----
        {
            const int nw = (g < 10) ? 768 : (g == 10 ? 1024 : 1536);
            const int ncol = nw / 64;
            for (int v = tid; v < nw; v += 256) {
                int k = v / ncol, j = v - k * ncol;
                int xi = (j < 12) ? (64 + 12 * g + j)
                                  : ((g == 10) ? (j - 12) : (12 * g - 128 + j - 12));
                sm[SM_WT + k * 24 + j] = w_in[xi * 64 + k];
            }
            for (int v = tid; v < 216; v += 256) {
                int cc = v / 27, t = v - cc * 27;
                int ch = 4 * g + (cc >> 1) + (cc & 1) * 64;
                sm[SM_GDW31 + cc * 56 + 2 * t]     = w_dw3a[ch * 27 + t];
                sm[SM_GDW31 + cc * 56 + 2 * t + 1] = w_dw1[ch * 27 + t];
            }
            if (tid < 72) {
                int cc = tid / 9, t = tid - cc * 9;
                int ch = 4 * g + (cc >> 1) + (cc & 1) * 64;
                sm[SM_GDW3B + cc * 12 + t] = w_dw3b[ch * 9 + t];
            }
            {
                int cpl = tid >> 6, o = tid & 63;
                sm[SM_GWOUT + tid] = w_out[o * 64 + 4 * g + cpl];
            }
        }
        __syncthreads();   // weights ready

        // ---- Phase A (channel-split, packed pairs) ----
        if (gh == 0) {
            if (doA) phaseA_B(sm, g, p0, m0, m1);
        } else if (doA) {
            if (g < 10)       phaseA_A<0>(sm, g, p0, m0, m1, pn00, pn01, pn10, pn11);
            else if (g == 10) phaseA_A<2>(sm, g, p0, m0, m1, pn00, pn01, pn10, pn11);
            else              phaseA_A<6>(sm, g, p0, m0, m1, pn00, pn01, pn10, pn11);
        }
        __syncthreads();   // XC ready

        // ---- Merged B1+B2 ({d3,d1} paired) + in-register B3 ----
        {
            const int cpl = warp >> 1, h = warp & 1;
            const int cc = cpl * 2 + h;
            const int cp = 4 * g + cpl;
            const bool ld = (lane < 20);

            u64 d[10];
            {
                float b3 = sm[SM_BDW3A + cp + h * 64];
                float b1 = sm[SM_BDW1 + cp + h * 64];
                u64 bp = pk2(b3, b1);
#pragma unroll
                for (int qy = 0; qy < 10; ++qy) d[qy] = bp;
            }

#pragma unroll
            for (int j = 0; j < 3; ++j) {
                u64 w[9];
#pragma unroll
                for (int t = 0; t < 9; ++t)
                    w[t] = lds64(sm + SM_GDW31 + cc * 56 + 2 * (j * 9 + t));
                const float* xc = sm + SM_XC + (h * 12 + 3 * cpl + j) * 240;
                float v0, q0, r0, v1, q1, r1, v2, q2, r2;
                {
                    float a = ld ? xc[lane] : 0.0f;
                    v0 = a;
                    q0 = __shfl_down_sync(0xffffffffu, a, 1);
                    r0 = __shfl_down_sync(0xffffffffu, a, 2);
                    float bva = ld ? xc[20 + lane] : 0.0f;
                    v1 = bva;
                    q1 = __shfl_down_sync(0xffffffffu, bva, 1);
                    r1 = __shfl_down_sync(0xffffffffu, bva, 2);
                }
#pragma unroll
                for (int qy = 0; qy < 10; ++qy) {
                    float c = ld ? xc[(qy + 2) * 20 + lane] : 0.0f;
                    v2 = c;
                    q2 = __shfl_down_sync(0xffffffffu, c, 1);
                    r2 = __shfl_down_sync(0xffffffffu, c, 2);

                    u64 dd = d[qy];
                    fma2(dd, w[0], pk2(v0, v0));
                    fma2(dd, w[1], pk2(q0, q0));
                    fma2(dd, w[2], pk2(r0, r0));
                    fma2(dd, w[3], pk2(v1, v1));
                    fma2(dd, w[4], pk2(q1, q1));
                    fma2(dd, w[5], pk2(r1, r1));
                    fma2(dd, w[6], pk2(v2, v2));
                    fma2(dd, w[7], pk2(q2, q2));
                    fma2(dd, w[8], pk2(r2, r2));
                    d[qy] = dd;

                    v0 = v1; q0 = q1; r0 = r1;
                    v1 = v2; q1 = q2; r1 = r2;
                }
            }

            // finalize: store d1, mask d3 in registers
            float e[10];
            {
                const bool stv = (lane < 18);
                const bool st1 = (lane >= 1 && lane <= 16);
                const int gxc  = bx0 + lane - 1;
                const bool colOK = stv && ((unsigned)gxc < 256u);
                float* dst1 = sm + SM_D1 + cc * 128;
#pragma unroll
                for (int qy = 0; qy < 10; ++qy) {
                    float d3, d1;
                    upk2(d[qy], d3, d1);
                    int gy = by0 + qy - 1;
                    bool ok = colOK && ((unsigned)gy < 256u);
                    e[qy] = ok ? d3 : 0.0f;
                    if (qy >= 1 && qy <= 8 && st1)
                        dst1[(qy - 1) * 16 + lane - 1] = d1;
                }
            }
            // B3 in-register
            {
                float e1[10], e2[10];
#pragma unroll
                for (int qy = 0; qy < 10; ++qy) {
                    e1[qy] = __shfl_down_sync(0xffffffffu, e[qy], 1);
                    e2[qy] = __shfl_down_sync(0xffffffffu, e[qy], 2);
                }
                float w3b[9];
#pragma unroll
                for (int t = 0; t < 9; ++t)
                    w3b[t] = sm[SM_GDW3B + cc * 12 + t];
                const float bb3 = sm[SM_BDW3B + cp + h * 64];
                float* dstb = sm + SM_D3B + cc * 128;
#pragma unroll
                for (int r = 0; r < 8; ++r) {
                    float o = bb3;
#pragma unroll
                    for (int ky = 0; ky < 3; ++ky) {
                        o = fmaf(w3b[3 * ky],     e[r + ky],  o);
                        o = fmaf(w3b[3 * ky + 1], e1[r + ky], o);
                        o = fmaf(w3b[3 * ky + 2], e2[r + ky], o);
                    }
                    if (lane < 16) dstb[r * 16 + lane] = o;
                }
            }
        }
        __syncthreads();   // D1 + D3B ready

        if (gh == 0) {
            // ---- gating + packed proj (o 0..31) from D1 ----
#pragma unroll
            for (int cpl = 0; cpl < 4; ++cpl) {
                float d1a = sm[SM_D1 + (cpl * 2 + 0) * 128 + tA];
                float d1b = sm[SM_D1 + (cpl * 2 + 1) * 128 + tA];
                float g1 = gelu_exact(d1a) * d1b;
                u64 g1p = pk2(g1, g1);
                const ulonglong2* wo = (const ulonglong2*)(sm + SM_GWOUT + cpl * 64);
#pragma unroll
                for (int mm = 0; mm < 8; ++mm) {
                    ulonglong2 w2 = wo[mm];
                    fma2(acc[2 * mm], w2.x, g1p);
                    fma2(acc[2 * mm + 1], w2.y, g1p);
                }
            }
        } else {
            // ---- gating + packed proj (o 32..63) from D3B ----
#pragma unroll
            for (int cpl = 0; cpl < 4; ++cpl) {
                float dA = sm[SM_D3B + (cpl * 2 + 0) * 128 + tA];
                float dB = sm[SM_D3B + (cpl * 2 + 1) * 128 + tA];
                float g2 = gelu_exact(dA) * dB;
                u64 g2p = pk2(g2, g2);
                const ulonglong2* wo = (const ulonglong2*)(sm + SM_GWOUT + cpl * 64 + 32);
#pragma unroll
                for (int mm = 0; mm < 8; ++mm) {
                    ulonglong2 w2 = wo[mm];
                    fma2(acc[2 * mm], w2.x, g2p);
                    fma2(acc[2 * mm + 1], w2.y, g2p);
                }
            }
        }
        __syncthreads();   // protect WT/GDW*/XC/D1/D3B before next staging
    }

    float* ob = out + (size_t)b * 64 * 65536 + (size_t)(by0 + tyl) * 256 + (bx0 + tx);
    const int o0 = gh * 32;
#pragma unroll
    for (int mm = 0; mm < 16; ++mm) {
        float lo, hi;
        upk2(acc[mm], lo, hi);
        ob[(size_t)(o0 + 2 * mm) * 65536]     = lo + sm[SM_BOUT + o0 + 2 * mm];
        ob[(size_t)(o0 + 2 * mm + 1) * 65536] = hi + sm[SM_BOUT + o0 + 2 * mm + 1];
    }
}

extern "C" void kernel_launch(void* const* d_in, const int* in_sizes, int n_in,
                              void* d_out, int out_size)
{
    (void)in_sizes; (void)n_in; (void)out_size;
    const float* x      = (const float*)d_in[0];
    const float* pneff  = (const float*)d_in[1];
    const float* w_in   = (const float*)d_in[2];
    const float* b_in   = (const float*)d_in[3];
    const float* w_pn   = (const float*)d_in[4];
    const float* b_pn   = (const float*)d_in[5];
    const float* w_dw1  = (const float*)d_in[6];
    const float* b_dw1  = (const float*)d_in[7];
    const float* w_dw3a = (const float*)d_in[8];
    const float* b_dw3a = (const float*)d_in[9];
    const float* w_dw3b = (const float*)d_in[10];
    const float* b_dw3b = (const float*)d_in[11];
    const float* w_out  = (const float*)d_in[12];
    const float* b_out  = (const float*)d_in[13];
    float* out = (float*)d_out;

    const size_t smem_bytes = SM_TOTAL * sizeof(float);
    cudaFuncSetAttribute(ffn_fused_kernel,
                         cudaFuncAttributeMaxDynamicSharedMemorySize,
                         (int)smem_bytes);
    dim3 grid(16, 32, 4);
    ffn_fused_kernel<<<grid, 256, smem_bytes>>>(
        x, pneff, w_in, b_in, w_pn, b_pn, w_dw1, b_dw1,
        w_dw3a, b_dw3a, w_dw3b, b_dw3b, w_out, b_out, out);
}